// round 1
// baseline (speedup 1.0000x reference)
#include <cuda_runtime.h>
#include <math.h>
#include <stdint.h>

#define BB 4
#define NN 100000
#define KK 16
#define EPSF 1e-6f
#define W_CE 2.0f
#define W_DICE 0.1f

// ---------------------------------------------------------------------------
// Global scratch (no allocations allowed)
// ---------------------------------------------------------------------------
struct Accum {
    float POS[BB][KK][KK];    // sum v * (-log2 m)[i] * gt[j]
    float TNEG[BB][KK][KK];   // sum v * (-log2(1-m))[i] * gt[j]
    float INTER[BB][KK][KK];  // sum v * m[i] * gt[j]
    float S1M[BB][KK];        // sum v * (-log2(1-m))[i]
    float SUMM[BB][KK];       // sum v * m[i]
    float SUMG[BB][KK];       // sum v * gt[j]
    float V[BB];              // sum v
};
__device__ Accum g_acc;

// ---------------------------------------------------------------------------
// Packed f32x2 helpers
// ---------------------------------------------------------------------------
__device__ __forceinline__ unsigned long long pack_dup(float x) {
    unsigned long long r;
    unsigned int u = __float_as_uint(x);
    asm("mov.b64 %0, {%1, %1};" : "=l"(r) : "r"(u));
    return r;
}
__device__ __forceinline__ void fma2(unsigned long long& acc,
                                     unsigned long long a,
                                     unsigned long long b) {
    asm("fma.rn.f32x2 %0, %1, %2, %0;" : "+l"(acc) : "l"(a), "l"(b));
}
__device__ __forceinline__ float lo32(unsigned long long x) {
    return __uint_as_float((unsigned int)(x & 0xffffffffULL));
}
__device__ __forceinline__ float hi32(unsigned long long x) {
    return __uint_as_float((unsigned int)(x >> 32));
}

// ---------------------------------------------------------------------------
// Kernel 0: zero the accumulators (graph-replay safe)
// ---------------------------------------------------------------------------
__global__ void zero_kernel() {
    float* p = (float*)&g_acc;
    const int n = (int)(sizeof(Accum) / sizeof(float));
    for (int idx = blockIdx.x * blockDim.x + threadIdx.x; idx < n;
         idx += gridDim.x * blockDim.x)
        p[idx] = 0.0f;
}

// ---------------------------------------------------------------------------
// Kernel 1: streaming reduction.
// Warp layout: lanes 0-15 handle row n0 (i = lane), lanes 16-31 handle row
// n0+1. mask/gt own-element loads are fully contiguous 128B per warp.
// Each half-warp broadcasts its gt row via 4x double2 (the b64 carriers feed
// fma.rn.f32x2 directly: pairs (g[2j], g[2j+1])).
// ---------------------------------------------------------------------------
__global__ void __launch_bounds__(256) accum_kernel(
    const float* __restrict__ mask,
    const float* __restrict__ gt,
    const float* __restrict__ valid) {
    const int b = blockIdx.y;
    const int lane = threadIdx.x & 31;
    const int warp = threadIdx.x >> 5;
    const int gwarp = blockIdx.x * (blockDim.x >> 5) + warp;
    const int nwarps = gridDim.x * (blockDim.x >> 5);
    const int i = lane & 15;
    const int half = lane >> 4;

    const float* mask_b = mask + (size_t)b * NN * KK;
    const float* gt_b = gt + (size_t)b * NN * KK;
    const float* val_b = valid + (size_t)b * NN;

    unsigned long long aP[8], aT[8], aI[8];
#pragma unroll
    for (int j = 0; j < 8; j++) { aP[j] = 0ull; aT[j] = 0ull; aI[j] = 0ull; }
    float s1m = 0.0f, smm = 0.0f, sgg = 0.0f, sv = 0.0f;

    const int NPAIR = NN / 2;
    for (int pr = gwarp; pr < NPAIR; pr += nwarps) {
        const int n0 = 2 * pr;
        const size_t rowoff = (size_t)n0 * KK;

        float m = mask_b[rowoff + lane];    // contiguous 128B / warp
        float go = gt_b[rowoff + lane];     // own j = i element
        float v = val_b[n0 + half];

        const double2* grow = (const double2*)(gt_b + rowoff + (size_t)half * KK);
        double2 d0 = grow[0], d1 = grow[1], d2 = grow[2], d3 = grow[3];
        unsigned long long g2[8];
        g2[0] = __double_as_longlong(d0.x); g2[1] = __double_as_longlong(d0.y);
        g2[2] = __double_as_longlong(d1.x); g2[3] = __double_as_longlong(d1.y);
        g2[4] = __double_as_longlong(d2.x); g2[5] = __double_as_longlong(d2.y);
        g2[6] = __double_as_longlong(d3.x); g2[7] = __double_as_longlong(d3.y);

        float mc = fminf(fmaxf(m, EPSF), 1.0f - EPSF);
        // accumulate in log2 space; scale by ln2 in finalize
        float p1 = -v * __log2f(mc);
        float q1 = -v * __log2f(1.0f - mc);
        float r1 = v * m;

        s1m += q1;
        smm += r1;
        sgg = fmaf(v, go, sgg);
        if (i == 0) sv += v;

        unsigned long long pp = pack_dup(p1);
        unsigned long long qq = pack_dup(q1);
        unsigned long long rr = pack_dup(r1);
#pragma unroll
        for (int j = 0; j < 8; j++) {
            fma2(aP[j], pp, g2[j]);
            fma2(aT[j], qq, g2[j]);
            fma2(aI[j], rr, g2[j]);
        }
    }

    // unpack to 16 floats each, fold upper half-warp into lower, atomically add
    float accP[16], accT[16], accI[16];
#pragma unroll
    for (int j = 0; j < 8; j++) {
        accP[2 * j] = lo32(aP[j]); accP[2 * j + 1] = hi32(aP[j]);
        accT[2 * j] = lo32(aT[j]); accT[2 * j + 1] = hi32(aT[j]);
        accI[2 * j] = lo32(aI[j]); accI[2 * j + 1] = hi32(aI[j]);
    }
#pragma unroll
    for (int j = 0; j < 16; j++) {
        accP[j] += __shfl_down_sync(0xffffffffu, accP[j], 16);
        accT[j] += __shfl_down_sync(0xffffffffu, accT[j], 16);
        accI[j] += __shfl_down_sync(0xffffffffu, accI[j], 16);
    }
    s1m += __shfl_down_sync(0xffffffffu, s1m, 16);
    smm += __shfl_down_sync(0xffffffffu, smm, 16);
    sgg += __shfl_down_sync(0xffffffffu, sgg, 16);
    sv += __shfl_down_sync(0xffffffffu, sv, 16);

    if (lane < 16) {
#pragma unroll
        for (int j = 0; j < 16; j++) {
            atomicAdd(&g_acc.POS[b][i][j], accP[j]);
            atomicAdd(&g_acc.TNEG[b][i][j], accT[j]);
            atomicAdd(&g_acc.INTER[b][i][j], accI[j]);
        }
        atomicAdd(&g_acc.S1M[b][i], s1m);
        atomicAdd(&g_acc.SUMM[b][i], smm);
        atomicAdd(&g_acc.SUMG[b][i], sgg);
        if (i == 0) atomicAdd(&g_acc.V[b], sv);
    }
}

// ---------------------------------------------------------------------------
// Kernel 2: build 16x16 cost per batch, Hungarian (JV shortest augmenting
// path, one warp-leader per batch => no intra-warp divergence), then loss.
// ---------------------------------------------------------------------------
__global__ void __launch_bounds__(256) finalize_kernel(float* __restrict__ out) {
    __shared__ float cost[BB][KK][KK];
    __shared__ int colmap[BB][KK];
    __shared__ float su[BB][KK + 1], svv[BB][KK + 1], sminv[BB][KK + 1];
    __shared__ int spcol[BB][KK + 1], sway[BB][KK + 1], sused[BB][KK + 1];
    __shared__ float rce[BB * KK], rdice[BB * KK];

    const float LN2 = 0.69314718055994530942f;
    const int t = threadIdx.x;

    for (int idx = t; idx < BB * KK * KK; idx += blockDim.x) {
        int b = idx / (KK * KK);
        int i = (idx / KK) % KK;
        int j = idx % KK;
        float denom = fmaxf(g_acc.V[b], 1.0f);
        float pos = LN2 * g_acc.POS[b][i][j];
        float neg = LN2 * (g_acc.S1M[b][i] - g_acc.TNEG[b][i][j]);
        float ce = (pos + neg) / denom;
        float dice = 1.0f - 2.0f * g_acc.INTER[b][i][j] /
                                (g_acc.SUMM[b][i] + g_acc.SUMG[b][j] + EPSF);
        cost[b][i][j] = W_CE * ce + W_DICE * dice;
    }
    __syncthreads();

    if ((t & 31) == 0 && (t >> 5) < BB) {
        const int b = t >> 5;
        float* u = su[b];
        float* vv = svv[b];
        float* minv = sminv[b];
        int* pcol = spcol[b];
        int* way = sway[b];
        int* used = sused[b];
        for (int j = 0; j <= KK; j++) { u[j] = 0.0f; vv[j] = 0.0f; pcol[j] = 0; }
        for (int ii = 1; ii <= KK; ii++) {
            pcol[0] = ii;
            int j0 = 0;
            for (int j = 0; j <= KK; j++) { minv[j] = 1e30f; used[j] = 0; }
            do {
                used[j0] = 1;
                int i0 = pcol[j0];
                int j1 = 0;
                float delta = 1e30f;
                for (int j = 1; j <= KK; j++) {
                    if (!used[j]) {
                        float cur = cost[b][i0 - 1][j - 1] - u[i0] - vv[j];
                        if (cur < minv[j]) { minv[j] = cur; way[j] = j0; }
                        if (minv[j] < delta) { delta = minv[j]; j1 = j; }
                    }
                }
                for (int j = 0; j <= KK; j++) {
                    if (used[j]) { u[pcol[j]] += delta; vv[j] -= delta; }
                    else minv[j] -= delta;
                }
                j0 = j1;
            } while (pcol[j0] != 0);
            do {
                int j1 = way[j0];
                pcol[j0] = pcol[j1];
                j0 = j1;
            } while (j0);
        }
        for (int j = 1; j <= KK; j++) colmap[b][pcol[j] - 1] = j - 1;
    }
    __syncthreads();

    if (t < BB * KK) {
        int b = t / KK, i = t % KK;
        int j = colmap[b][i];
        rce[t] = LN2 * (g_acc.POS[b][i][j] + g_acc.S1M[b][i] - g_acc.TNEG[b][i][j]);
        rdice[t] = 1.0f - 2.0f * g_acc.INTER[b][i][j] /
                              (g_acc.SUMM[b][i] + g_acc.SUMG[b][j] + EPSF);
    }
    __syncthreads();

    if (t == 0) {
        float cs = 0.0f, ds = 0.0f, vt = 0.0f;
        for (int x = 0; x < BB * KK; x++) { cs += rce[x]; ds += rdice[x]; }
        for (int b = 0; b < BB; b++) vt += g_acc.V[b];
        float l_ce = cs / (fmaxf(vt, 1.0f) * (float)KK);
        float l_dice = ds / (float)(BB * KK);
        out[0] = W_CE * l_ce + W_DICE * l_dice;
    }
}

// ---------------------------------------------------------------------------
extern "C" void kernel_launch(void* const* d_in, const int* in_sizes, int n_in,
                              void* d_out, int out_size) {
    const float* mask = (const float*)d_in[0];
    const float* gt = (const float*)d_in[1];
    const float* valid = (const float*)d_in[2];
    float* out = (float*)d_out;

    zero_kernel<<<8, 256>>>();
    dim3 grid(160, BB);
    accum_kernel<<<grid, 256>>>(mask, gt, valid);
    finalize_kernel<<<1, 256>>>(out);
}

// round 2
// speedup vs baseline: 1.5163x; 1.5163x over previous
#include <cuda_runtime.h>
#include <math.h>
#include <stdint.h>

#define BB 4
#define NN 100000
#define KK 16
#define EPSF 1e-6f
#define W_CE 2.0f
#define W_DICE 0.1f

// ---------------------------------------------------------------------------
// Global scratch (no allocations allowed)
// ---------------------------------------------------------------------------
struct Accum {
    float POS[BB][KK][KK];    // sum v * (-log2 m)[i] * gt[j]
    float TNEG[BB][KK][KK];   // sum v * (-log2(1-m))[i] * gt[j]
    float INTER[BB][KK][KK];  // sum v * m[i] * gt[j]
    float S1M[BB][KK];        // sum v * (-log2(1-m))[i]
    float SUMM[BB][KK];       // sum v * m[i]
    float SUMG[BB][KK];       // sum v * gt[j]
    float V[BB];              // sum v
};
__device__ Accum g_acc;

// ---------------------------------------------------------------------------
// Packed f32x2 helpers
// ---------------------------------------------------------------------------
__device__ __forceinline__ unsigned long long pack_dup(float x) {
    unsigned long long r;
    unsigned int u = __float_as_uint(x);
    asm("mov.b64 %0, {%1, %1};" : "=l"(r) : "r"(u));
    return r;
}
__device__ __forceinline__ void fma2(unsigned long long& acc,
                                     unsigned long long a,
                                     unsigned long long b) {
    asm("fma.rn.f32x2 %0, %1, %2, %0;" : "+l"(acc) : "l"(a), "l"(b));
}
__device__ __forceinline__ float lo32(unsigned long long x) {
    return __uint_as_float((unsigned int)(x & 0xffffffffULL));
}
__device__ __forceinline__ float hi32(unsigned long long x) {
    return __uint_as_float((unsigned int)(x >> 32));
}

// ---------------------------------------------------------------------------
// Kernel 0: zero the accumulators (graph-replay safe)
// ---------------------------------------------------------------------------
__global__ void zero_kernel() {
    float* p = (float*)&g_acc;
    const int n = (int)(sizeof(Accum) / sizeof(float));
    for (int idx = blockIdx.x * blockDim.x + threadIdx.x; idx < n;
         idx += gridDim.x * blockDim.x)
        p[idx] = 0.0f;
}

// ---------------------------------------------------------------------------
// Kernel 1: streaming reduction.
// Warp layout: lanes 0-15 handle row n0 (i = lane), lanes 16-31 handle row
// n0+1. mask/gt own-element loads are fully contiguous 128B per warp.
// Each half-warp broadcasts its gt row via 4x double2 (the b64 carriers feed
// fma.rn.f32x2 directly: pairs (g[2j], g[2j+1])).
// ---------------------------------------------------------------------------
__global__ void __launch_bounds__(256) accum_kernel(
    const float* __restrict__ mask,
    const float* __restrict__ gt,
    const float* __restrict__ valid) {
    const int b = blockIdx.y;
    const int lane = threadIdx.x & 31;
    const int warp = threadIdx.x >> 5;
    const int gwarp = blockIdx.x * (blockDim.x >> 5) + warp;
    const int nwarps = gridDim.x * (blockDim.x >> 5);
    const int i = lane & 15;
    const int half = lane >> 4;

    const float* mask_b = mask + (size_t)b * NN * KK;
    const float* gt_b = gt + (size_t)b * NN * KK;
    const float* val_b = valid + (size_t)b * NN;

    unsigned long long aP[8], aT[8], aI[8];
#pragma unroll
    for (int j = 0; j < 8; j++) { aP[j] = 0ull; aT[j] = 0ull; aI[j] = 0ull; }
    float s1m = 0.0f, smm = 0.0f, sgg = 0.0f, sv = 0.0f;

    const int NPAIR = NN / 2;
    for (int pr = gwarp; pr < NPAIR; pr += nwarps) {
        const int n0 = 2 * pr;
        const size_t rowoff = (size_t)n0 * KK;

        float m = mask_b[rowoff + lane];    // contiguous 128B / warp
        float go = gt_b[rowoff + lane];     // own j = i element
        float v = val_b[n0 + half];

        const double2* grow = (const double2*)(gt_b + rowoff + (size_t)half * KK);
        double2 d0 = grow[0], d1 = grow[1], d2 = grow[2], d3 = grow[3];
        unsigned long long g2[8];
        g2[0] = __double_as_longlong(d0.x); g2[1] = __double_as_longlong(d0.y);
        g2[2] = __double_as_longlong(d1.x); g2[3] = __double_as_longlong(d1.y);
        g2[4] = __double_as_longlong(d2.x); g2[5] = __double_as_longlong(d2.y);
        g2[6] = __double_as_longlong(d3.x); g2[7] = __double_as_longlong(d3.y);

        float mc = fminf(fmaxf(m, EPSF), 1.0f - EPSF);
        // accumulate in log2 space; scale by ln2 in finalize
        float p1 = -v * __log2f(mc);
        float q1 = -v * __log2f(1.0f - mc);
        float r1 = v * m;

        s1m += q1;
        smm += r1;
        sgg = fmaf(v, go, sgg);
        if (i == 0) sv += v;

        unsigned long long pp = pack_dup(p1);
        unsigned long long qq = pack_dup(q1);
        unsigned long long rr = pack_dup(r1);
#pragma unroll
        for (int j = 0; j < 8; j++) {
            fma2(aP[j], pp, g2[j]);
            fma2(aT[j], qq, g2[j]);
            fma2(aI[j], rr, g2[j]);
        }
    }

    // unpack to 16 floats each, fold upper half-warp into lower, atomically add
    float accP[16], accT[16], accI[16];
#pragma unroll
    for (int j = 0; j < 8; j++) {
        accP[2 * j] = lo32(aP[j]); accP[2 * j + 1] = hi32(aP[j]);
        accT[2 * j] = lo32(aT[j]); accT[2 * j + 1] = hi32(aT[j]);
        accI[2 * j] = lo32(aI[j]); accI[2 * j + 1] = hi32(aI[j]);
    }
#pragma unroll
    for (int j = 0; j < 16; j++) {
        accP[j] += __shfl_down_sync(0xffffffffu, accP[j], 16);
        accT[j] += __shfl_down_sync(0xffffffffu, accT[j], 16);
        accI[j] += __shfl_down_sync(0xffffffffu, accI[j], 16);
    }
    s1m += __shfl_down_sync(0xffffffffu, s1m, 16);
    smm += __shfl_down_sync(0xffffffffu, smm, 16);
    sgg += __shfl_down_sync(0xffffffffu, sgg, 16);
    sv += __shfl_down_sync(0xffffffffu, sv, 16);

    if (lane < 16) {
#pragma unroll
        for (int j = 0; j < 16; j++) {
            atomicAdd(&g_acc.POS[b][i][j], accP[j]);
            atomicAdd(&g_acc.TNEG[b][i][j], accT[j]);
            atomicAdd(&g_acc.INTER[b][i][j], accI[j]);
        }
        atomicAdd(&g_acc.S1M[b][i], s1m);
        atomicAdd(&g_acc.SUMM[b][i], smm);
        atomicAdd(&g_acc.SUMG[b][i], sgg);
        if (i == 0) atomicAdd(&g_acc.V[b], sv);
    }
}

// ---------------------------------------------------------------------------
// Kernel 2: build 16x16 cost per batch, then WARP-PARALLEL Hungarian (JV
// shortest augmenting path). One warp per batch. Lane j owns column j
// (vv/minv/way/used/pcol live in registers); lane i owns u[i] plus a
// row-coverage flag. Per do-iteration: 1 LDS + a few SHFLs + shfl-min
// reduction, instead of ~80 serial shared-memory ops.
// Tie-break: ballot+ffs picks the lowest column among equal minima, matching
// the serial scan's strict-< first-min rule exactly.
// ---------------------------------------------------------------------------
__global__ void __launch_bounds__(256) finalize_kernel(float* __restrict__ out) {
    __shared__ float cost[BB][KK][KK];
    __shared__ int colmap[BB][KK];
    __shared__ float rce[BB * KK], rdice[BB * KK];

    const float LN2 = 0.69314718055994530942f;
    const unsigned FULL = 0xffffffffu;
    const int t = threadIdx.x;

    for (int idx = t; idx < BB * KK * KK; idx += blockDim.x) {
        int b = idx / (KK * KK);
        int i = (idx / KK) % KK;
        int j = idx % KK;
        float denom = fmaxf(g_acc.V[b], 1.0f);
        float pos = LN2 * g_acc.POS[b][i][j];
        float neg = LN2 * (g_acc.S1M[b][i] - g_acc.TNEG[b][i][j]);
        float ce = (pos + neg) / denom;
        float dice = 1.0f - 2.0f * g_acc.INTER[b][i][j] /
                                (g_acc.SUMM[b][i] + g_acc.SUMG[b][j] + EPSF);
        cost[b][i][j] = W_CE * ce + W_DICE * dice;
    }
    __syncthreads();

    const int w = t >> 5;
    const int lane = t & 31;
    if (w < BB) {
        const int b = w;
        // Column index space: 0 = sentinel, 1..KK = real columns (lane = col).
        float ur = 0.0f;   // lane i holds u[i] (rows 1..KK at lanes 1..KK)
        float vv = 0.0f;   // lane j holds v[j]
        int pcol = 0;      // lane j holds row matched to column j (0 = free)

        for (int ii = 1; ii <= KK; ii++) {
            if (lane == 0) pcol = ii;
            float minv = 1e30f;
            int way = 0;
            int used = 0;
            int rowcov = 0;   // lane i: row i on alternating tree
            int j0 = 0;

            while (true) {
                if (lane == j0) used = 1;
                int i0 = __shfl_sync(FULL, pcol, j0);
                if (lane == i0) rowcov = 1;
                float u_i0 = __shfl_sync(FULL, ur, i0);

                int active = (lane >= 1 && lane <= KK && !used);
                if (active) {
                    float c = cost[b][i0 - 1][lane - 1];
                    float cur = c - u_i0 - vv;
                    if (cur < minv) { minv = cur; way = j0; }
                }
                float val = active ? minv : 1e30f;
                float red = val;
#pragma unroll
                for (int off = 16; off; off >>= 1)
                    red = fminf(red, __shfl_xor_sync(FULL, red, off));
                unsigned bal = __ballot_sync(FULL, val == red);
                int j1 = __ffs(bal) - 1;
                float delta = red;

                if (rowcov) ur += delta;
                if (used) vv -= delta;
                else if (lane >= 1 && lane <= KK) minv -= delta;

                j0 = j1;
                int pj = __shfl_sync(FULL, pcol, j0);
                if (pj == 0) break;
            }
            // augment along alternating path
            while (j0 != 0) {
                int j1 = __shfl_sync(FULL, way, j0);
                int pv = __shfl_sync(FULL, pcol, j1);
                if (lane == j0) pcol = pv;
                j0 = j1;
            }
        }
        if (lane >= 1 && lane <= KK) colmap[b][pcol - 1] = lane - 1;
    }
    __syncthreads();

    if (t < BB * KK) {
        int b = t / KK, i = t % KK;
        int j = colmap[b][i];
        rce[t] = LN2 * (g_acc.POS[b][i][j] + g_acc.S1M[b][i] - g_acc.TNEG[b][i][j]);
        rdice[t] = 1.0f - 2.0f * g_acc.INTER[b][i][j] /
                              (g_acc.SUMM[b][i] + g_acc.SUMG[b][j] + EPSF);
    }
    __syncthreads();

    if (t == 0) {
        float cs = 0.0f, ds = 0.0f, vt = 0.0f;
        for (int x = 0; x < BB * KK; x++) { cs += rce[x]; ds += rdice[x]; }
        for (int b = 0; b < BB; b++) vt += g_acc.V[b];
        float l_ce = cs / (fmaxf(vt, 1.0f) * (float)KK);
        float l_dice = ds / (float)(BB * KK);
        out[0] = W_CE * l_ce + W_DICE * l_dice;
    }
}

// ---------------------------------------------------------------------------
extern "C" void kernel_launch(void* const* d_in, const int* in_sizes, int n_in,
                              void* d_out, int out_size) {
    const float* mask = (const float*)d_in[0];
    const float* gt = (const float*)d_in[1];
    const float* valid = (const float*)d_in[2];
    float* out = (float*)d_out;

    zero_kernel<<<8, 256>>>();
    dim3 grid(160, BB);
    accum_kernel<<<grid, 256>>>(mask, gt, valid);
    finalize_kernel<<<1, 256>>>(out);
}

// round 3
// speedup vs baseline: 7.2050x; 4.7518x over previous
#include <cuda_runtime.h>
#include <math.h>
#include <stdint.h>

#define BB 4
#define NN 100000
#define KK 16
#define EPSF 1e-6f
#define W_CE 2.0f
#define W_DICE 0.1f

#define GX 74                 // blocks per batch
#define NBLK (GX * BB)        // 296 total blocks
#define NWPB 8                // warps per block (256 threads)
#define ENT 832               // padded entries per partial slot
// entry layout per batch slot: [0,256) POS, [256,512) TNEG, [512,768) INTER,
// [768,784) S1M[i], [784,800) SUMM[i], [800,816) SUMG[j], [816] V
#define NE_REAL 817
#define NE_TOT (BB * NE_REAL) // 3268

struct Part { float e[ENT]; };
__device__ Part g_part[NBLK];
__device__ int g_count;       // self-resetting: last block writes 0

// ---------------------------------------------------------------------------
__device__ __forceinline__ unsigned long long pack_dup(float x) {
    unsigned long long r;
    unsigned int u = __float_as_uint(x);
    asm("mov.b64 %0, {%1, %1};" : "=l"(r) : "r"(u));
    return r;
}
__device__ __forceinline__ void fma2(unsigned long long& acc,
                                     unsigned long long a,
                                     unsigned long long b) {
    asm("fma.rn.f32x2 %0, %1, %2, %0;" : "+l"(acc) : "l"(a), "l"(b));
}
__device__ __forceinline__ float lo32(unsigned long long x) {
    return __uint_as_float((unsigned int)(x & 0xffffffffULL));
}
__device__ __forceinline__ float hi32(unsigned long long x) {
    return __uint_as_float((unsigned int)(x >> 32));
}

// ---------------------------------------------------------------------------
// Single fused kernel.
// ---------------------------------------------------------------------------
__global__ void __launch_bounds__(256, 2) fused_kernel(
    const float* __restrict__ mask,
    const float* __restrict__ gt,
    const float* __restrict__ valid,
    float* __restrict__ out) {
    __shared__ float pti[NWPB][768];                  // per-warp P/T/I partials
    __shared__ float v1m[NWPB][32], vmm[NWPB][32], vgg[NWPB][32];
    __shared__ float vvs[NWPB];
    __shared__ float facc[NE_TOT];                    // final sums (last block)
    __shared__ float cost[BB][KK][KK];
    __shared__ int colmap[BB][KK];
    __shared__ float rce[BB * KK], rdice[BB * KK];
    __shared__ int is_last;

    const int b = blockIdx.y;
    const int t = threadIdx.x;
    const int lane = t & 31;
    const int w = t >> 5;
    const int i = lane & 15;   // row-of-cost index owned by this lane
    const int jh = lane >> 4;  // j-half owned (0: j 0-7, 1: j 8-15); also row-of-pair
    const int gwarp = blockIdx.x * NWPB + w;
    const int nw = GX * NWPB;  // warps per batch

    const float* mask_b = mask + (size_t)b * NN * KK;
    const float* gt_b = gt + (size_t)b * NN * KK;
    const float* val_b = valid + (size_t)b * NN;

    // 12 u64 accumulators: aX[k] covers j = jh*8 + {2k, 2k+1}
    unsigned long long aP[4], aT[4], aI[4];
#pragma unroll
    for (int k = 0; k < 4; k++) { aP[k] = 0ull; aT[k] = 0ull; aI[k] = 0ull; }
    float s1m = 0.0f, smm = 0.0f, sgg = 0.0f, sv = 0.0f;

    const int NPAIR = NN / 2;
    for (int pr = gwarp; pr < NPAIR; pr += nw) {
        const int n0 = 2 * pr;
        const size_t ro = (size_t)n0 * KK;

        float m = __ldg(mask_b + ro + lane);   // (row jh, col i), 128B coalesced
        float go = __ldg(gt_b + ro + lane);    // (row jh, col i)
        float2 v2 = *(const float2*)(val_b + n0);
        float vown = jh ? v2.y : v2.x;

        // gt chunk for my j-half: own row (jh) and other row (1-jh)
        const float* base = gt_b + ro;
        ulonglong2 o0 = *(const ulonglong2*)(base + jh * 24);      // row jh,   j jh*8..+4
        ulonglong2 o1 = *(const ulonglong2*)(base + jh * 24 + 4);  //           j jh*8+4..+8
        ulonglong2 x0 = *(const ulonglong2*)(base + 16 - 8 * jh);  // row 1-jh, j jh*8..+4
        ulonglong2 x1 = *(const ulonglong2*)(base + 20 - 8 * jh);

        float mc = fminf(fmaxf(m, EPSF), 1.0f - EPSF);
        float pown = -vown * __log2f(mc);          // log2-space; *ln2 at the end
        float qown = -vown * __log2f(1.0f - mc);
        float rown = vown * m;
        float poth = __shfl_xor_sync(0xffffffffu, pown, 16);
        float qoth = __shfl_xor_sync(0xffffffffu, qown, 16);
        float roth = __shfl_xor_sync(0xffffffffu, rown, 16);

        s1m += qown;
        smm += rown;
        sgg = fmaf(vown, go, sgg);
        if (lane == 0) sv += v2.x + v2.y;

        unsigned long long Pw = pack_dup(pown), Qw = pack_dup(qown), Rw = pack_dup(rown);
        unsigned long long Px = pack_dup(poth), Qx = pack_dup(qoth), Rx = pack_dup(roth);

        fma2(aP[0], Pw, o0.x); fma2(aP[1], Pw, o0.y);
        fma2(aP[2], Pw, o1.x); fma2(aP[3], Pw, o1.y);
        fma2(aT[0], Qw, o0.x); fma2(aT[1], Qw, o0.y);
        fma2(aT[2], Qw, o1.x); fma2(aT[3], Qw, o1.y);
        fma2(aI[0], Rw, o0.x); fma2(aI[1], Rw, o0.y);
        fma2(aI[2], Rw, o1.x); fma2(aI[3], Rw, o1.y);

        fma2(aP[0], Px, x0.x); fma2(aP[1], Px, x0.y);
        fma2(aP[2], Px, x1.x); fma2(aP[3], Px, x1.y);
        fma2(aT[0], Qx, x0.x); fma2(aT[1], Qx, x0.y);
        fma2(aT[2], Qx, x1.x); fma2(aT[3], Qx, x1.y);
        fma2(aI[0], Rx, x0.x); fma2(aI[1], Rx, x0.y);
        fma2(aI[2], Rx, x1.x); fma2(aI[3], Rx, x1.y);
    }

    // ---- per-warp -> shared ----
    {
        const int basej = i * 16 + jh * 8;
#pragma unroll
        for (int k = 0; k < 4; k++) {
            pti[w][basej + 2 * k] = lo32(aP[k]);
            pti[w][basej + 2 * k + 1] = hi32(aP[k]);
            pti[w][256 + basej + 2 * k] = lo32(aT[k]);
            pti[w][256 + basej + 2 * k + 1] = hi32(aT[k]);
            pti[w][512 + basej + 2 * k] = lo32(aI[k]);
            pti[w][512 + basej + 2 * k + 1] = hi32(aI[k]);
        }
        v1m[w][lane] = s1m;
        vmm[w][lane] = smm;
        vgg[w][lane] = sgg;
        if (lane == 0) vvs[w] = sv;
    }
    __syncthreads();

    // ---- block reduce -> deterministic per-block partial slot ----
    Part* gp = &g_part[b * GX + blockIdx.x];
    for (int e = t; e < 768; e += 256) {
        float s = 0.0f;
#pragma unroll
        for (int ww = 0; ww < NWPB; ww++) s += pti[ww][e];
        gp->e[e] = s;
    }
    if (t < 16) {
        float s = 0.0f;
#pragma unroll
        for (int ww = 0; ww < NWPB; ww++) s += v1m[ww][t] + v1m[ww][t + 16];
        gp->e[768 + t] = s;
    } else if (t < 32) {
        int q = t - 16;
        float s = 0.0f;
#pragma unroll
        for (int ww = 0; ww < NWPB; ww++) s += vmm[ww][q] + vmm[ww][q + 16];
        gp->e[784 + q] = s;
    } else if (t < 48) {
        int q = t - 32;
        float s = 0.0f;
#pragma unroll
        for (int ww = 0; ww < NWPB; ww++) s += vgg[ww][q] + vgg[ww][q + 16];
        gp->e[800 + q] = s;
    } else if (t == 48) {
        float s = 0.0f;
#pragma unroll
        for (int ww = 0; ww < NWPB; ww++) s += vvs[ww];
        gp->e[816] = s;
    }

    __threadfence();
    __syncthreads();
    if (t == 0) {
        int old = atomicAdd(&g_count, 1);
        is_last = (old == NBLK - 1);
    }
    __syncthreads();
    if (!is_last) return;

    if (t == 0) g_count = 0;  // graph-replay safe

    // ---- final reduce: 13-way jammed for MLP ----
    {
        float s[13];
        const float* bas[13];
        int ok[13];
#pragma unroll
        for (int k = 0; k < 13; k++) {
            int q = t + k * 256;
            ok[k] = (q < NE_TOT);
            s[k] = 0.0f;
            if (ok[k]) {
                int bb2 = q / NE_REAL;
                int e = q - bb2 * NE_REAL;
                bas[k] = &g_part[bb2 * GX].e[e];
            } else {
                bas[k] = &g_part[0].e[0];
            }
        }
        for (int gx = 0; gx < GX; gx++) {
#pragma unroll
            for (int k = 0; k < 13; k++)
                if (ok[k]) s[k] += bas[k][(size_t)gx * ENT];
        }
#pragma unroll
        for (int k = 0; k < 13; k++) {
            int q = t + k * 256;
            if (ok[k]) facc[q] = s[k];
        }
    }
    __syncthreads();

    // ---- cost matrices ----
    const float LN2 = 0.69314718055994530942f;
    for (int idx = t; idx < BB * 256; idx += 256) {
        int bb2 = idx >> 8;
        int r = idx & 255;
        int ii = r >> 4, jj = r & 15;
        const float* F = facc + bb2 * NE_REAL;
        float denom = fmaxf(F[816], 1.0f);
        float pos = LN2 * F[ii * 16 + jj];
        float neg = LN2 * (F[768 + ii] - F[256 + ii * 16 + jj]);
        float ce = (pos + neg) / denom;
        float dice = 1.0f - 2.0f * F[512 + ii * 16 + jj] /
                                (F[784 + ii] + F[800 + jj] + EPSF);
        cost[bb2][ii][jj] = W_CE * ce + W_DICE * dice;
    }
    __syncthreads();

    // ---- warp-parallel Hungarian (JV), one warp per batch ----
    const unsigned FULL = 0xffffffffu;
    if (w < BB) {
        const int bb2 = w;
        float ur = 0.0f;
        float vv = 0.0f;
        int pcol = 0;

        for (int ii = 1; ii <= KK; ii++) {
            if (lane == 0) pcol = ii;
            float minv = 1e30f;
            int way = 0;
            int used = 0;
            int rowcov = 0;
            int j0 = 0;

            while (true) {
                if (lane == j0) used = 1;
                int i0 = __shfl_sync(FULL, pcol, j0);
                if (lane == i0) rowcov = 1;
                float u_i0 = __shfl_sync(FULL, ur, i0);

                int active = (lane >= 1 && lane <= KK && !used);
                if (active) {
                    float c = cost[bb2][i0 - 1][lane - 1];
                    float cur = c - u_i0 - vv;
                    if (cur < minv) { minv = cur; way = j0; }
                }
                float val = active ? minv : 1e30f;
                float red = val;
#pragma unroll
                for (int off = 16; off; off >>= 1)
                    red = fminf(red, __shfl_xor_sync(FULL, red, off));
                unsigned bal = __ballot_sync(FULL, val == red);
                int j1 = __ffs(bal) - 1;
                float delta = red;

                if (rowcov) ur += delta;
                if (used) vv -= delta;
                else if (lane >= 1 && lane <= KK) minv -= delta;

                j0 = j1;
                int pj = __shfl_sync(FULL, pcol, j0);
                if (pj == 0) break;
            }
            while (j0 != 0) {
                int j1 = __shfl_sync(FULL, way, j0);
                int pv = __shfl_sync(FULL, pcol, j1);
                if (lane == j0) pcol = pv;
                j0 = j1;
            }
        }
        if (lane >= 1 && lane <= KK) colmap[bb2][pcol - 1] = lane - 1;
    }
    __syncthreads();

    // ---- loss ----
    if (t < BB * KK) {
        int bb2 = t / KK, ii = t % KK;
        int jj = colmap[bb2][ii];
        const float* F = facc + bb2 * NE_REAL;
        rce[t] = LN2 * (F[ii * 16 + jj] + F[768 + ii] - F[256 + ii * 16 + jj]);
        rdice[t] = 1.0f - 2.0f * F[512 + ii * 16 + jj] /
                              (F[784 + ii] + F[800 + jj] + EPSF);
    }
    __syncthreads();

    if (t == 0) {
        float cs = 0.0f, ds = 0.0f, vt = 0.0f;
        for (int x = 0; x < BB * KK; x++) { cs += rce[x]; ds += rdice[x]; }
        for (int bb2 = 0; bb2 < BB; bb2++) vt += facc[bb2 * NE_REAL + 816];
        float l_ce = cs / (fmaxf(vt, 1.0f) * (float)KK);
        float l_dice = ds / (float)(BB * KK);
        out[0] = W_CE * l_ce + W_DICE * l_dice;
    }
}

// ---------------------------------------------------------------------------
extern "C" void kernel_launch(void* const* d_in, const int* in_sizes, int n_in,
                              void* d_out, int out_size) {
    const float* mask = (const float*)d_in[0];
    const float* gt = (const float*)d_in[1];
    const float* valid = (const float*)d_in[2];
    float* out = (float*)d_out;

    dim3 grid(GX, BB);
    fused_kernel<<<grid, 256>>>(mask, gt, valid, out);
}

// round 4
// speedup vs baseline: 7.3784x; 1.0241x over previous
#include <cuda_runtime.h>
#include <math.h>
#include <stdint.h>

#define BB 4
#define NN 100000
#define KK 16
#define EPSF 1e-6f
#define W_CE 2.0f
#define W_DICE 0.1f

#define GX 111                // blocks per batch
#define NBLK (GX * BB)        // 444 total blocks = 3 per SM
#define NWPB 8                // warps per block (256 threads)
#define ENT 768               // entries per partial slot: POS | TNEG | INTER
#define NE_TOT (BB * ENT)     // 3072 = 12 * 256

struct Part { float e[ENT]; };
__device__ Part g_part[NBLK];
__device__ int g_count;       // self-resetting: last block writes 0

// ---------------------------------------------------------------------------
__device__ __forceinline__ unsigned long long pack_dup(float x) {
    unsigned long long r;
    unsigned int u = __float_as_uint(x);
    asm("mov.b64 %0, {%1, %1};" : "=l"(r) : "r"(u));
    return r;
}
__device__ __forceinline__ void fma2(unsigned long long& acc,
                                     unsigned long long a,
                                     unsigned long long b) {
    asm("fma.rn.f32x2 %0, %1, %2, %0;" : "+l"(acc) : "l"(a), "l"(b));
}
__device__ __forceinline__ float lo32(unsigned long long x) {
    return __uint_as_float((unsigned int)(x & 0xffffffffULL));
}
__device__ __forceinline__ float hi32(unsigned long long x) {
    return __uint_as_float((unsigned int)(x >> 32));
}

// ---------------------------------------------------------------------------
// Single fused kernel. Marginals (S1M/SUMM/SUMG/V) are derived in the
// epilogue from row/col sums of TNEG/INTER (gt one-hot => exact; softmax row
// sum = 1 to 1e-7 for V).
// ---------------------------------------------------------------------------
__global__ void __launch_bounds__(256, 3) fused_kernel(
    const float* __restrict__ mask,
    const float* __restrict__ gt,
    const float* __restrict__ valid,
    float* __restrict__ out) {
    __shared__ float pti[NWPB][ENT];   // per-warp P/T/I partials
    __shared__ float facc[NE_TOT];     // final sums (last block only)
    __shared__ float cost[BB][KK][KK];
    __shared__ float mS1M[BB][KK], mSUMM[BB][KK], mSUMG[BB][KK], mV[BB];
    __shared__ int colmap[BB][KK];
    __shared__ float rce[BB * KK], rdice[BB * KK];
    __shared__ int is_last;

    const int b = blockIdx.y;
    const int t = threadIdx.x;
    const int lane = t & 31;
    const int w = t >> 5;
    const int i = lane & 15;   // cost-row index owned by this lane
    const int jh = lane >> 4;  // j-half owned; also row-of-pair for p/q/r
    const int gwarp = blockIdx.x * NWPB + w;
    const int nw = GX * NWPB;  // warps per batch

    const float* mask_b = mask + (size_t)b * NN * KK;
    const float* gt_b = gt + (size_t)b * NN * KK;
    const float* val_b = valid + (size_t)b * NN;

    // 12 u64 accumulators: aX[k] covers j = jh*8 + {2k, 2k+1}
    unsigned long long aP[4], aT[4], aI[4];
#pragma unroll
    for (int k = 0; k < 4; k++) { aP[k] = 0ull; aT[k] = 0ull; aI[k] = 0ull; }

    const int NPAIR = NN / 2;
#pragma unroll 2
    for (int pr = gwarp; pr < NPAIR; pr += nw) {
        const int n0 = 2 * pr;
        const size_t ro = (size_t)n0 * KK;

        float m = __ldg(mask_b + ro + lane);   // (row jh, col i), coalesced
        float2 v2 = *(const float2*)(val_b + n0);
        float vown = jh ? v2.y : v2.x;

        const float* base = gt_b + ro;
        ulonglong2 o0 = *(const ulonglong2*)(base + jh * 24);      // own row
        ulonglong2 o1 = *(const ulonglong2*)(base + jh * 24 + 4);
        ulonglong2 x0 = *(const ulonglong2*)(base + 16 - 8 * jh);  // other row
        ulonglong2 x1 = *(const ulonglong2*)(base + 20 - 8 * jh);

        float mc = fminf(fmaxf(m, EPSF), 1.0f - EPSF);
        float nv = -vown;
        float pown = nv * __log2f(mc);         // log2-space; *ln2 at the end
        float qown = nv * __log2f(1.0f - mc);
        float rown = vown * m;
        float poth = __shfl_xor_sync(0xffffffffu, pown, 16);
        float qoth = __shfl_xor_sync(0xffffffffu, qown, 16);
        float roth = __shfl_xor_sync(0xffffffffu, rown, 16);

        unsigned long long Pw = pack_dup(pown), Qw = pack_dup(qown), Rw = pack_dup(rown);
        unsigned long long Px = pack_dup(poth), Qx = pack_dup(qoth), Rx = pack_dup(roth);

        fma2(aP[0], Pw, o0.x); fma2(aP[1], Pw, o0.y);
        fma2(aP[2], Pw, o1.x); fma2(aP[3], Pw, o1.y);
        fma2(aT[0], Qw, o0.x); fma2(aT[1], Qw, o0.y);
        fma2(aT[2], Qw, o1.x); fma2(aT[3], Qw, o1.y);
        fma2(aI[0], Rw, o0.x); fma2(aI[1], Rw, o0.y);
        fma2(aI[2], Rw, o1.x); fma2(aI[3], Rw, o1.y);

        fma2(aP[0], Px, x0.x); fma2(aP[1], Px, x0.y);
        fma2(aP[2], Px, x1.x); fma2(aP[3], Px, x1.y);
        fma2(aT[0], Qx, x0.x); fma2(aT[1], Qx, x0.y);
        fma2(aT[2], Qx, x1.x); fma2(aT[3], Qx, x1.y);
        fma2(aI[0], Rx, x0.x); fma2(aI[1], Rx, x0.y);
        fma2(aI[2], Rx, x1.x); fma2(aI[3], Rx, x1.y);
    }

    // ---- per-warp -> shared ----
    {
        const int basej = i * 16 + jh * 8;
#pragma unroll
        for (int k = 0; k < 4; k++) {
            pti[w][basej + 2 * k] = lo32(aP[k]);
            pti[w][basej + 2 * k + 1] = hi32(aP[k]);
            pti[w][256 + basej + 2 * k] = lo32(aT[k]);
            pti[w][256 + basej + 2 * k + 1] = hi32(aT[k]);
            pti[w][512 + basej + 2 * k] = lo32(aI[k]);
            pti[w][512 + basej + 2 * k + 1] = hi32(aI[k]);
        }
    }
    __syncthreads();

    // ---- block reduce -> deterministic per-block partial slot ----
    Part* gp = &g_part[b * GX + blockIdx.x];
    for (int e = t; e < ENT; e += 256) {
        float s = 0.0f;
#pragma unroll
        for (int ww = 0; ww < NWPB; ww++) s += pti[ww][e];
        gp->e[e] = s;
    }

    __threadfence();
    __syncthreads();
    if (t == 0) {
        int old = atomicAdd(&g_count, 1);
        is_last = (old == NBLK - 1);
    }
    __syncthreads();
    if (!is_last) return;

    if (t == 0) g_count = 0;  // graph-replay safe

    // ---- final reduce: 12 entries per thread, jammed for MLP ----
    {
        float s[12];
        const float* bas[12];
#pragma unroll
        for (int k = 0; k < 12; k++) {
            int q = t + k * 256;
            int bb2 = q / ENT;
            int e = q - bb2 * ENT;
            bas[k] = &g_part[bb2 * GX].e[e];
            s[k] = 0.0f;
        }
        for (int gx = 0; gx < GX; gx++) {
#pragma unroll
            for (int k = 0; k < 12; k++) s[k] += bas[k][(size_t)gx * ENT];
        }
#pragma unroll
        for (int k = 0; k < 12; k++) facc[t + k * 256] = s[k];
    }
    __syncthreads();

    // ---- derive marginals from TNEG / INTER ----
    if (t < BB * KK) {
        int bb2 = t / KK, q = t % KK;
        const float* F = facc + bb2 * ENT;
        float s1m = 0.0f, summ = 0.0f, sumg = 0.0f;
#pragma unroll
        for (int x = 0; x < KK; x++) {
            s1m += F[256 + q * 16 + x];   // row sum of TNEG
            summ += F[512 + q * 16 + x];  // row sum of INTER
            sumg += F[512 + x * 16 + q];  // col sum of INTER
        }
        mS1M[bb2][q] = s1m;
        mSUMM[bb2][q] = summ;
        mSUMG[bb2][q] = sumg;
    }
    __syncthreads();
    if (t < BB) {
        float v = 0.0f;
#pragma unroll
        for (int x = 0; x < KK; x++) v += mSUMG[t][x];
        mV[t] = v;
    }
    __syncthreads();

    // ---- cost matrices ----
    const float LN2 = 0.69314718055994530942f;
    for (int idx = t; idx < BB * 256; idx += 256) {
        int bb2 = idx >> 8;
        int r = idx & 255;
        int ii = r >> 4, jj = r & 15;
        const float* F = facc + bb2 * ENT;
        float denom = fmaxf(mV[bb2], 1.0f);
        float pos = LN2 * F[ii * 16 + jj];
        float neg = LN2 * (mS1M[bb2][ii] - F[256 + ii * 16 + jj]);
        float ce = (pos + neg) / denom;
        float dice = 1.0f - 2.0f * F[512 + ii * 16 + jj] /
                                (mSUMM[bb2][ii] + mSUMG[bb2][jj] + EPSF);
        cost[bb2][ii][jj] = W_CE * ce + W_DICE * dice;
    }
    __syncthreads();

    // ---- warp-parallel Hungarian (JV), one warp per batch ----
    const unsigned FULL = 0xffffffffu;
    if (w < BB) {
        const int bb2 = w;
        float ur = 0.0f;
        float vv = 0.0f;
        int pcol = 0;

        for (int ii = 1; ii <= KK; ii++) {
            if (lane == 0) pcol = ii;
            float minv = 1e30f;
            int way = 0;
            int used = 0;
            int rowcov = 0;
            int j0 = 0;

            while (true) {
                if (lane == j0) used = 1;
                int i0 = __shfl_sync(FULL, pcol, j0);
                if (lane == i0) rowcov = 1;
                float u_i0 = __shfl_sync(FULL, ur, i0);

                int active = (lane >= 1 && lane <= KK && !used);
                if (active) {
                    float c = cost[bb2][i0 - 1][lane - 1];
                    float cur = c - u_i0 - vv;
                    if (cur < minv) { minv = cur; way = j0; }
                }
                float val = active ? minv : 1e30f;
                float red = val;
#pragma unroll
                for (int off = 16; off; off >>= 1)
                    red = fminf(red, __shfl_xor_sync(FULL, red, off));
                unsigned bal = __ballot_sync(FULL, val == red);
                int j1 = __ffs(bal) - 1;
                float delta = red;

                if (rowcov) ur += delta;
                if (used) vv -= delta;
                else if (lane >= 1 && lane <= KK) minv -= delta;

                j0 = j1;
                int pj = __shfl_sync(FULL, pcol, j0);
                if (pj == 0) break;
            }
            while (j0 != 0) {
                int j1 = __shfl_sync(FULL, way, j0);
                int pv = __shfl_sync(FULL, pcol, j1);
                if (lane == j0) pcol = pv;
                j0 = j1;
            }
        }
        if (lane >= 1 && lane <= KK) colmap[bb2][pcol - 1] = lane - 1;
    }
    __syncthreads();

    // ---- loss ----
    if (t < BB * KK) {
        int bb2 = t / KK, ii = t % KK;
        int jj = colmap[bb2][ii];
        const float* F = facc + bb2 * ENT;
        rce[t] = LN2 * (F[ii * 16 + jj] + mS1M[bb2][ii] - F[256 + ii * 16 + jj]);
        rdice[t] = 1.0f - 2.0f * F[512 + ii * 16 + jj] /
                              (mSUMM[bb2][ii] + mSUMG[bb2][jj] + EPSF);
    }
    __syncthreads();

    if (t == 0) {
        float cs = 0.0f, ds = 0.0f, vt = 0.0f;
        for (int x = 0; x < BB * KK; x++) { cs += rce[x]; ds += rdice[x]; }
        for (int bb2 = 0; bb2 < BB; bb2++) vt += mV[bb2];
        float l_ce = cs / (fmaxf(vt, 1.0f) * (float)KK);
        float l_dice = ds / (float)(BB * KK);
        out[0] = W_CE * l_ce + W_DICE * l_dice;
    }
}

// ---------------------------------------------------------------------------
extern "C" void kernel_launch(void* const* d_in, const int* in_sizes, int n_in,
                              void* d_out, int out_size) {
    const float* mask = (const float*)d_in[0];
    const float* gt = (const float*)d_in[1];
    const float* valid = (const float*)d_in[2];
    float* out = (float*)d_out;

    dim3 grid(GX, BB);
    fused_kernel<<<grid, 256>>>(mask, gt, valid, out);
}